// round 14
// baseline (speedup 1.0000x reference)
#include <cuda_runtime.h>
#include <cmath>
#include <complex>
#include <vector>
#include <algorithm>
#include <cstdint>

// ---------------------------------------------------------------------------
// Host-side exact e3nn real-basis Wigner 3j (mirrors reference_code line by line)
// ---------------------------------------------------------------------------
namespace cgh {
typedef std::complex<double> cd;

static double fct(int n) { double r = 1.0; for (int i = 2; i <= n; ++i) r *= (double)i; return r; }

static double su2_cg_coeff(int j1, int m1, int j2, int m2, int j3, int m3) {
    if (m3 != m1 + m2) return 0.0;
    int vmin = std::max(std::max(-j1 + j2 + m3, -j1 + m1), 0);
    int vmax = std::min(std::min(j2 + j3 + m1, j3 - j1 + j2), j3 + m3);
    double C = std::sqrt((2.0 * j3 + 1.0) * fct(j3 + j1 - j2) * fct(j3 - j1 + j2) * fct(j1 + j2 - j3)
                         * fct(j3 + m3) * fct(j3 - m3)
                         / (fct(j1 + j2 + j3 + 1) * fct(j1 - m1) * fct(j1 + m1) * fct(j2 - m2) * fct(j2 + m2)));
    double S = 0.0;
    for (int v = vmin; v <= vmax; ++v) {
        double sgn = ((v + j2 + m2) & 1) ? -1.0 : 1.0;
        S += sgn * fct(j2 + j3 + m1 - v) * fct(j1 - m1 + v)
             / (fct(v) * fct(j3 - j1 + j2 - v) * fct(j3 + m3 - v) * fct(v + j1 - j2 - m3));
    }
    return C * S;
}

static void su2_cg(int j1, int j2, int j3, double* mat) {
    int d1 = 2 * j1 + 1, d2 = 2 * j2 + 1, d3 = 2 * j3 + 1;
    for (int i = 0; i < d1 * d2 * d3; ++i) mat[i] = 0.0;
    if (std::abs(j1 - j2) <= j3 && j3 <= j1 + j2) {
        for (int m1 = -j1; m1 <= j1; ++m1)
            for (int m2 = -j2; m2 <= j2; ++m2)
                if (std::abs(m1 + m2) <= j3)
                    mat[((j1 + m1) * d2 + (j2 + m2)) * d3 + (j3 + m1 + m2)] =
                        su2_cg_coeff(j1, m1, j2, m2, j3, m1 + m2);
    }
    double s = 1.0 / std::sqrt(2.0 * j3 + 1.0);
    for (int i = 0; i < d1 * d2 * d3; ++i) mat[i] *= s;
}

static void basis_r2c(int l, cd* q) {
    int d = 2 * l + 1;
    for (int i = 0; i < d * d; ++i) q[i] = cd(0, 0);
    const double inv = 1.0 / std::sqrt(2.0);
    for (int m = -l; m < 0; ++m) {
        q[(l + m) * d + (l - m)] = cd(inv, 0);
        q[(l + m) * d + (l + m)] = cd(0, -inv);
    }
    q[l * d + l] = cd(1, 0);
    for (int m = 1; m <= l; ++m) {
        double sgn = (m & 1) ? -1.0 : 1.0;
        q[(l + m) * d + (l + m)] = cd(sgn * inv, 0);
        q[(l + m) * d + (l - m)] = cd(0, sgn * inv);
    }
    cd ph(1, 0), mi(0, -1);
    for (int t = 0; t < l; ++t) ph *= mi;
    for (int i = 0; i < d * d; ++i) q[i] *= ph;
}

static void wigner3j(int l1, int l2, int l3, double* out) {
    int d1 = 2 * l1 + 1, d2 = 2 * l2 + 1, d3 = 2 * l3 + 1;
    std::vector<cd> Q1(d1 * d1), Q2(d2 * d2), Q3(d3 * d3);
    basis_r2c(l1, Q1.data()); basis_r2c(l2, Q2.data()); basis_r2c(l3, Q3.data());
    std::vector<double> C(d1 * d2 * d3);
    su2_cg(l1, l2, l3, C.data());
    double nrm = 0.0;
    for (int j = 0; j < d1; ++j)
        for (int ll = 0; ll < d2; ++ll)
            for (int m = 0; m < d3; ++m) {
                cd s(0, 0);
                for (int i = 0; i < d1; ++i)
                    for (int k = 0; k < d2; ++k)
                        for (int n = 0; n < d3; ++n)
                            s += Q1[i * d1 + j] * Q2[k * d2 + ll] * std::conj(Q3[n * d3 + m])
                                 * C[(i * d2 + k) * d3 + n];
                out[(j * d2 + ll) * d3 + m] = s.real();
                nrm += s.real() * s.real();
            }
    nrm = std::sqrt(nrm);
    for (int i = 0; i < d1 * d2 * d3; ++i) out[i] /= nrm;
}
} // namespace cgh

// ---------------------------------------------------------------------------
struct Consts {
    float c000;
    float c2[3];      // 0e x 1o -> 1o : diag
    float c101[3];    // 1o x 0e -> 1o : diag
    float c330[3];    // 1o x 1o -> 0e : diag
    float c4[6];      // 1o x 1o -> 1e
    float c5[11];     // 1o x 1o -> 2e
};

static Consts build_consts() {
    Consts K;
    const double s3 = std::sqrt(3.0), s5 = std::sqrt(5.0);
    double w000[1];  cgh::wigner3j(0, 0, 0, w000);
    K.c000 = (float)(w000[0]);
    double w011[9];  cgh::wigner3j(0, 1, 1, w011);
    for (int k = 0; k < 3; ++k) K.c2[k] = (float)(w011[k * 3 + k] * s3);
    double w101[9];  cgh::wigner3j(1, 0, 1, w101);
    for (int k = 0; k < 3; ++k) K.c101[k] = (float)(w101[k * 3 + k] * s3);
    double w110[9];  cgh::wigner3j(1, 1, 0, w110);
    for (int i = 0; i < 3; ++i) K.c330[i] = (float)(w110[i * 3 + i]);
    double w111[27]; cgh::wigner3j(1, 1, 1, w111);
    K.c4[0] = (float)(w111[(1 * 3 + 2) * 3 + 0] * s3);
    K.c4[1] = (float)(w111[(2 * 3 + 1) * 3 + 0] * s3);
    K.c4[2] = (float)(w111[(0 * 3 + 2) * 3 + 1] * s3);
    K.c4[3] = (float)(w111[(2 * 3 + 0) * 3 + 1] * s3);
    K.c4[4] = (float)(w111[(0 * 3 + 1) * 3 + 2] * s3);
    K.c4[5] = (float)(w111[(1 * 3 + 0) * 3 + 2] * s3);
    double w112[45]; cgh::wigner3j(1, 1, 2, w112);
    K.c5[0]  = (float)(w112[(0 * 3 + 2) * 5 + 0] * s5);
    K.c5[1]  = (float)(w112[(2 * 3 + 0) * 5 + 0] * s5);
    K.c5[2]  = (float)(w112[(0 * 3 + 1) * 5 + 1] * s5);
    K.c5[3]  = (float)(w112[(1 * 3 + 0) * 5 + 1] * s5);
    K.c5[4]  = (float)(w112[(0 * 3 + 0) * 5 + 2] * s5);
    K.c5[5]  = (float)(w112[(1 * 3 + 1) * 5 + 2] * s5);
    K.c5[6]  = (float)(w112[(2 * 3 + 2) * 5 + 2] * s5);
    K.c5[7]  = (float)(w112[(1 * 3 + 2) * 5 + 3] * s5);
    K.c5[8]  = (float)(w112[(2 * 3 + 1) * 5 + 3] * s5);
    K.c5[9]  = (float)(w112[(0 * 3 + 0) * 5 + 4] * s5);
    K.c5[10] = (float)(w112[(2 * 3 + 2) * 5 + 4] * s5);
    return K;
}

// ---------------------------------------------------------------------------
// FINAL converged kernel (v11). Session result: 45.6 -> 41.0 us, ~81% of HBM
// write spec; four independent designs confirm this is the DRAM/L2 wall.
//
// Design facts established this session:
//  - 2 q/thread @ 32 regs is the sweet spot (4 q/thread spills -> 2x slower).
//  - Warp-local smem staging + __syncwarp beats block barriers.
//  - Fire-and-forget __stcs beats TMA bulk stores in steady-state replay
//    (TMA wins single-launch ncu but pays a CTA drain tail every replay).
//  - Occupancy >= ~74% is sufficient; beyond that, timing is flat.
//  - Compiler magic-multiply division beats hand strength-reduction here.
//
// Warp w handles q in [q0 + 64w, q0 + 64w + 64); lane l handles q = base+2l.
// Warp region (float offsets from wb = 896*w):
//   seg2 @wb+0, seg3 @wb+192, seg4 @wb+384 (192 each), seg5 @wb+576 (320).
// Output row segment bases: 0, 2048, 4096, 10240, 16384, 22528.
//
// Gather maps (flat slice pos p -> row-major array index), q even:
//   a0 : u*8192 + (q>>6)*256 + (q&63)
//   a1i: p=(i*64+u)*2048+q ; 64 + (p/192)*256 + p%192
//   b0 : v*8192 + (q>>5)*128 + (q&31)
//   b1i: p=(i*32+v)*2048+q ; 32 + (p/96)*128  + p%96
// ---------------------------------------------------------------------------
__global__ __launch_bounds__(256, 8)
void ftp_kernel(const float* __restrict__ in1, const float* __restrict__ in2,
                float* __restrict__ out, Consts K)
{
    __shared__ __align__(16) float stage[7168];
    const int tid  = threadIdx.x;
    const int lane = tid & 31;
    const int w    = tid >> 5;
    const int bid  = blockIdx.x;
    const int row  = bid >> 2;            // 4 tiles of 512q per row
    const int u = row >> 5;
    const int v = row & 31;
    const int q0 = (bid & 3) << 9;        // tile start in q
    const int qw = q0 + (w << 6);         // warp's 64-q slice start
    const int q  = qw + 2 * lane;         // this thread's (even) q
    float* __restrict__ orow = out + (size_t)row * 32768;
    float* const wstage = stage + w * 896;

    // ---- gathers (all L2/L1-resident, contiguous float2) ----
    const float2 A0 = *(const float2*)(in1 + (u * 8192 + ((q >> 6) << 8) + (q & 63)));
    unsigned p = (unsigned)(u * 2048 + q);
    const float2 A1x = *(const float2*)(in1 + 64 + (p / 192u) * 256 + (p % 192u));
    p += 131072u;
    const float2 A1y = *(const float2*)(in1 + 64 + (p / 192u) * 256 + (p % 192u));
    p += 131072u;
    const float2 A1z = *(const float2*)(in1 + 64 + (p / 192u) * 256 + (p % 192u));
    const float2 B0 = *(const float2*)(in2 + (v * 8192 + ((q >> 5) << 7) + (q & 31)));
    p = (unsigned)(v * 2048 + q);
    const float2 B1x = *(const float2*)(in2 + 32 + (p / 96u) * 128 + (p % 96u));
    p += 65536u;
    const float2 B1y = *(const float2*)(in2 + 32 + (p / 96u) * 128 + (p % 96u));
    p += 65536u;
    const float2 B1z = *(const float2*)(in2 + 32 + (p / 96u) * 128 + (p % 96u));

    // ---- seg0 / seg1: direct coalesced streaming stores ----
    float2 t2;
    t2.x = K.c000 * A0.x * B0.x;
    t2.y = K.c000 * A0.y * B0.y;
    __stcs((float2*)(orow + q), t2);
    t2.x = K.c330[0] * A1x.x * B1x.x + K.c330[1] * A1y.x * B1y.x + K.c330[2] * A1z.x * B1z.x;
    t2.y = K.c330[0] * A1x.y * B1x.y + K.c330[1] * A1y.y * B1y.y + K.c330[2] * A1z.y * B1z.y;
    __stcs((float2*)(orow + 2048 + q), t2);

    // ---- seg2: 0e x 1o -> 1o (layout q*3+k) @wb+0 ----
    {
        const float a0 = A0.x, b0 = A0.y;
        float2 s;
        s.x = K.c2[0] * a0 * B1x.x;  s.y = K.c2[1] * a0 * B1y.x;
        *(float2*)(wstage + 6 * lane) = s;
        s.x = K.c2[2] * a0 * B1z.x;  s.y = K.c2[0] * b0 * B1x.y;
        *(float2*)(wstage + 6 * lane + 2) = s;
        s.x = K.c2[1] * b0 * B1y.y;  s.y = K.c2[2] * b0 * B1z.y;
        *(float2*)(wstage + 6 * lane + 4) = s;
    }
    // ---- seg3: 1o x 0e -> 1o @wb+192 ----
    {
        const float b0 = B0.x, c0 = B0.y;
        float2 s;
        s.x = K.c101[0] * A1x.x * b0;  s.y = K.c101[1] * A1y.x * b0;
        *(float2*)(wstage + 192 + 6 * lane) = s;
        s.x = K.c101[2] * A1z.x * b0;  s.y = K.c101[0] * A1x.y * c0;
        *(float2*)(wstage + 192 + 6 * lane + 2) = s;
        s.x = K.c101[1] * A1y.y * c0;  s.y = K.c101[2] * A1z.y * c0;
        *(float2*)(wstage + 192 + 6 * lane + 4) = s;
    }
    // ---- seg4: 1o x 1o -> 1e (Levi-Civita) @wb+384 ----
    {
        float2 s;
        s.x = K.c4[0] * A1y.x * B1z.x + K.c4[1] * A1z.x * B1y.x;
        s.y = K.c4[2] * A1x.x * B1z.x + K.c4[3] * A1z.x * B1x.x;
        *(float2*)(wstage + 384 + 6 * lane) = s;
        s.x = K.c4[4] * A1x.x * B1y.x + K.c4[5] * A1y.x * B1x.x;
        s.y = K.c4[0] * A1y.y * B1z.y + K.c4[1] * A1z.y * B1y.y;
        *(float2*)(wstage + 384 + 6 * lane + 2) = s;
        s.x = K.c4[2] * A1x.y * B1z.y + K.c4[3] * A1z.y * B1x.y;
        s.y = K.c4[4] * A1x.y * B1y.y + K.c4[5] * A1y.y * B1x.y;
        *(float2*)(wstage + 384 + 6 * lane + 4) = s;
    }
    // ---- seg5: 1o x 1o -> 2e (layout q*5+k) @wb+576 ----
    {
        float2 s;
        s.x = K.c5[0] * A1x.x * B1z.x + K.c5[1]  * A1z.x * B1x.x;
        s.y = K.c5[2] * A1x.x * B1y.x + K.c5[3]  * A1y.x * B1x.x;
        *(float2*)(wstage + 576 + 10 * lane) = s;
        s.x = K.c5[4] * A1x.x * B1x.x + K.c5[5]  * A1y.x * B1y.x + K.c5[6] * A1z.x * B1z.x;
        s.y = K.c5[7] * A1y.x * B1z.x + K.c5[8]  * A1z.x * B1y.x;
        *(float2*)(wstage + 576 + 10 * lane + 2) = s;
        s.x = K.c5[9] * A1x.x * B1x.x + K.c5[10] * A1z.x * B1z.x;
        s.y = K.c5[0] * A1x.y * B1z.y + K.c5[1]  * A1z.y * B1x.y;
        *(float2*)(wstage + 576 + 10 * lane + 4) = s;
        s.x = K.c5[2] * A1x.y * B1y.y + K.c5[3]  * A1y.y * B1x.y;
        s.y = K.c5[4] * A1x.y * B1x.y + K.c5[5]  * A1y.y * B1y.y + K.c5[6] * A1z.y * B1z.y;
        *(float2*)(wstage + 576 + 10 * lane + 6) = s;
        s.x = K.c5[7] * A1y.y * B1z.y + K.c5[8]  * A1z.y * B1y.y;
        s.y = K.c5[9] * A1x.y * B1x.y + K.c5[10] * A1z.y * B1z.y;
        *(float2*)(wstage + 576 + 10 * lane + 8) = s;
    }

    __syncwarp();   // warp-local: staging visible to flush within this warp

    // ---- flush: warp's own 224 float4 = exactly 7 per lane, coalesced ----
    const float4* const wstage4 = reinterpret_cast<const float4*>(wstage);
    #pragma unroll
    for (int it = 0; it < 7; ++it) {
        const int t = it * 32 + lane;      // 0..223 within warp region
        const float4 val = wstage4[t];
        int addr;
        if (t < 48)       addr = 4096  + qw * 3 + 4 * t;
        else if (t < 96)  addr = 10240 + qw * 3 + 4 * (t - 48);
        else if (t < 144) addr = 16384 + qw * 3 + 4 * (t - 96);
        else              addr = 22528 + qw * 5 + 4 * (t - 144);
        __stcs(reinterpret_cast<float4*>(orow + addr), val);
    }
}

// ---------------------------------------------------------------------------
extern "C" void kernel_launch(void* const* d_in, const int* in_sizes, int n_in,
                              void* d_out, int out_size)
{
    (void)n_in; (void)out_size;
    Consts K = build_consts();                  // pure host math, deterministic
    const float* in1 = (const float*)d_in[0];   // (2048, 256) fp32
    const float* in2 = (const float*)d_in[1];   // (2048, 128) fp32
    float* out = (float*)d_out;                 // (2048, 32768) fp32
    const int rows = in_sizes[0] / 256;         // 2048 output rows == (u,v) pairs
    ftp_kernel<<<rows * 4, 256>>>(in1, in2, out, K);
}

// round 15
// speedup vs baseline: 1.0023x; 1.0023x over previous
#include <cuda_runtime.h>
#include <cmath>
#include <complex>
#include <vector>
#include <algorithm>
#include <cstdint>

// ---------------------------------------------------------------------------
// Host-side exact e3nn real-basis Wigner 3j (mirrors reference_code line by line)
// ---------------------------------------------------------------------------
namespace cgh {
typedef std::complex<double> cd;

static double fct(int n) { double r = 1.0; for (int i = 2; i <= n; ++i) r *= (double)i; return r; }

static double su2_cg_coeff(int j1, int m1, int j2, int m2, int j3, int m3) {
    if (m3 != m1 + m2) return 0.0;
    int vmin = std::max(std::max(-j1 + j2 + m3, -j1 + m1), 0);
    int vmax = std::min(std::min(j2 + j3 + m1, j3 - j1 + j2), j3 + m3);
    double C = std::sqrt((2.0 * j3 + 1.0) * fct(j3 + j1 - j2) * fct(j3 - j1 + j2) * fct(j1 + j2 - j3)
                         * fct(j3 + m3) * fct(j3 - m3)
                         / (fct(j1 + j2 + j3 + 1) * fct(j1 - m1) * fct(j1 + m1) * fct(j2 - m2) * fct(j2 + m2)));
    double S = 0.0;
    for (int v = vmin; v <= vmax; ++v) {
        double sgn = ((v + j2 + m2) & 1) ? -1.0 : 1.0;
        S += sgn * fct(j2 + j3 + m1 - v) * fct(j1 - m1 + v)
             / (fct(v) * fct(j3 - j1 + j2 - v) * fct(j3 + m3 - v) * fct(v + j1 - j2 - m3));
    }
    return C * S;
}

static void su2_cg(int j1, int j2, int j3, double* mat) {
    int d1 = 2 * j1 + 1, d2 = 2 * j2 + 1, d3 = 2 * j3 + 1;
    for (int i = 0; i < d1 * d2 * d3; ++i) mat[i] = 0.0;
    if (std::abs(j1 - j2) <= j3 && j3 <= j1 + j2) {
        for (int m1 = -j1; m1 <= j1; ++m1)
            for (int m2 = -j2; m2 <= j2; ++m2)
                if (std::abs(m1 + m2) <= j3)
                    mat[((j1 + m1) * d2 + (j2 + m2)) * d3 + (j3 + m1 + m2)] =
                        su2_cg_coeff(j1, m1, j2, m2, j3, m1 + m2);
    }
    double s = 1.0 / std::sqrt(2.0 * j3 + 1.0);
    for (int i = 0; i < d1 * d2 * d3; ++i) mat[i] *= s;
}

static void basis_r2c(int l, cd* q) {
    int d = 2 * l + 1;
    for (int i = 0; i < d * d; ++i) q[i] = cd(0, 0);
    const double inv = 1.0 / std::sqrt(2.0);
    for (int m = -l; m < 0; ++m) {
        q[(l + m) * d + (l - m)] = cd(inv, 0);
        q[(l + m) * d + (l + m)] = cd(0, -inv);
    }
    q[l * d + l] = cd(1, 0);
    for (int m = 1; m <= l; ++m) {
        double sgn = (m & 1) ? -1.0 : 1.0;
        q[(l + m) * d + (l + m)] = cd(sgn * inv, 0);
        q[(l + m) * d + (l - m)] = cd(0, sgn * inv);
    }
    cd ph(1, 0), mi(0, -1);
    for (int t = 0; t < l; ++t) ph *= mi;
    for (int i = 0; i < d * d; ++i) q[i] *= ph;
}

static void wigner3j(int l1, int l2, int l3, double* out) {
    int d1 = 2 * l1 + 1, d2 = 2 * l2 + 1, d3 = 2 * l3 + 1;
    std::vector<cd> Q1(d1 * d1), Q2(d2 * d2), Q3(d3 * d3);
    basis_r2c(l1, Q1.data()); basis_r2c(l2, Q2.data()); basis_r2c(l3, Q3.data());
    std::vector<double> C(d1 * d2 * d3);
    su2_cg(l1, l2, l3, C.data());
    double nrm = 0.0;
    for (int j = 0; j < d1; ++j)
        for (int ll = 0; ll < d2; ++ll)
            for (int m = 0; m < d3; ++m) {
                cd s(0, 0);
                for (int i = 0; i < d1; ++i)
                    for (int k = 0; k < d2; ++k)
                        for (int n = 0; n < d3; ++n)
                            s += Q1[i * d1 + j] * Q2[k * d2 + ll] * std::conj(Q3[n * d3 + m])
                                 * C[(i * d2 + k) * d3 + n];
                out[(j * d2 + ll) * d3 + m] = s.real();
                nrm += s.real() * s.real();
            }
    nrm = std::sqrt(nrm);
    for (int i = 0; i < d1 * d2 * d3; ++i) out[i] /= nrm;
}
} // namespace cgh

// ---------------------------------------------------------------------------
struct Consts {
    float c000;
    float c2[3];      // 0e x 1o -> 1o : diag
    float c101[3];    // 1o x 0e -> 1o : diag
    float c330[3];    // 1o x 1o -> 0e : diag
    float c4[6];      // 1o x 1o -> 1e
    float c5[11];     // 1o x 1o -> 2e
};

static Consts build_consts() {
    Consts K;
    const double s3 = std::sqrt(3.0), s5 = std::sqrt(5.0);
    double w000[1];  cgh::wigner3j(0, 0, 0, w000);
    K.c000 = (float)(w000[0]);
    double w011[9];  cgh::wigner3j(0, 1, 1, w011);
    for (int k = 0; k < 3; ++k) K.c2[k] = (float)(w011[k * 3 + k] * s3);
    double w101[9];  cgh::wigner3j(1, 0, 1, w101);
    for (int k = 0; k < 3; ++k) K.c101[k] = (float)(w101[k * 3 + k] * s3);
    double w110[9];  cgh::wigner3j(1, 1, 0, w110);
    for (int i = 0; i < 3; ++i) K.c330[i] = (float)(w110[i * 3 + i]);
    double w111[27]; cgh::wigner3j(1, 1, 1, w111);
    K.c4[0] = (float)(w111[(1 * 3 + 2) * 3 + 0] * s3);
    K.c4[1] = (float)(w111[(2 * 3 + 1) * 3 + 0] * s3);
    K.c4[2] = (float)(w111[(0 * 3 + 2) * 3 + 1] * s3);
    K.c4[3] = (float)(w111[(2 * 3 + 0) * 3 + 1] * s3);
    K.c4[4] = (float)(w111[(0 * 3 + 1) * 3 + 2] * s3);
    K.c4[5] = (float)(w111[(1 * 3 + 0) * 3 + 2] * s3);
    double w112[45]; cgh::wigner3j(1, 1, 2, w112);
    K.c5[0]  = (float)(w112[(0 * 3 + 2) * 5 + 0] * s5);
    K.c5[1]  = (float)(w112[(2 * 3 + 0) * 5 + 0] * s5);
    K.c5[2]  = (float)(w112[(0 * 3 + 1) * 5 + 1] * s5);
    K.c5[3]  = (float)(w112[(1 * 3 + 0) * 5 + 1] * s5);
    K.c5[4]  = (float)(w112[(0 * 3 + 0) * 5 + 2] * s5);
    K.c5[5]  = (float)(w112[(1 * 3 + 1) * 5 + 2] * s5);
    K.c5[6]  = (float)(w112[(2 * 3 + 2) * 5 + 2] * s5);
    K.c5[7]  = (float)(w112[(1 * 3 + 2) * 5 + 3] * s5);
    K.c5[8]  = (float)(w112[(2 * 3 + 1) * 5 + 3] * s5);
    K.c5[9]  = (float)(w112[(0 * 3 + 0) * 5 + 4] * s5);
    K.c5[10] = (float)(w112[(2 * 3 + 2) * 5 + 4] * s5);
    return K;
}

// ---------------------------------------------------------------------------
// FINAL converged kernel (v11). Session result: 45.6 -> 41.0 us, ~81% of HBM
// write spec; five independent design families confirm the DRAM/L2 wall.
// Run-to-run band of this exact configuration: 41.02-41.12 us.
//
// Design facts established this session:
//  - 2 q/thread @ 32 regs is the sweet spot (4 q/thread spills -> 2x slower).
//  - Warp-local smem staging + __syncwarp beats block barriers.
//  - Fire-and-forget __stcs beats TMA bulk stores in steady-state replay
//    (TMA wins single-launch ncu but pays a CTA drain tail every replay).
//  - Occupancy >= ~74% is sufficient; beyond that, timing is flat.
//  - Compiler magic-multiply division beats hand strength-reduction here.
//
// Warp w handles q in [q0 + 64w, q0 + 64w + 64); lane l handles q = base+2l.
// Warp region (float offsets from wb = 896*w):
//   seg2 @wb+0, seg3 @wb+192, seg4 @wb+384 (192 each), seg5 @wb+576 (320).
// Output row segment bases: 0, 2048, 4096, 10240, 16384, 22528.
//
// Gather maps (flat slice pos p -> row-major array index), q even:
//   a0 : u*8192 + (q>>6)*256 + (q&63)
//   a1i: p=(i*64+u)*2048+q ; 64 + (p/192)*256 + p%192
//   b0 : v*8192 + (q>>5)*128 + (q&31)
//   b1i: p=(i*32+v)*2048+q ; 32 + (p/96)*128  + p%96
// ---------------------------------------------------------------------------
__global__ __launch_bounds__(256, 8)
void ftp_kernel(const float* __restrict__ in1, const float* __restrict__ in2,
                float* __restrict__ out, Consts K)
{
    __shared__ __align__(16) float stage[7168];
    const int tid  = threadIdx.x;
    const int lane = tid & 31;
    const int w    = tid >> 5;
    const int bid  = blockIdx.x;
    const int row  = bid >> 2;            // 4 tiles of 512q per row
    const int u = row >> 5;
    const int v = row & 31;
    const int q0 = (bid & 3) << 9;        // tile start in q
    const int qw = q0 + (w << 6);         // warp's 64-q slice start
    const int q  = qw + 2 * lane;         // this thread's (even) q
    float* __restrict__ orow = out + (size_t)row * 32768;
    float* const wstage = stage + w * 896;

    // ---- gathers (all L2/L1-resident, contiguous float2) ----
    const float2 A0 = *(const float2*)(in1 + (u * 8192 + ((q >> 6) << 8) + (q & 63)));
    unsigned p = (unsigned)(u * 2048 + q);
    const float2 A1x = *(const float2*)(in1 + 64 + (p / 192u) * 256 + (p % 192u));
    p += 131072u;
    const float2 A1y = *(const float2*)(in1 + 64 + (p / 192u) * 256 + (p % 192u));
    p += 131072u;
    const float2 A1z = *(const float2*)(in1 + 64 + (p / 192u) * 256 + (p % 192u));
    const float2 B0 = *(const float2*)(in2 + (v * 8192 + ((q >> 5) << 7) + (q & 31)));
    p = (unsigned)(v * 2048 + q);
    const float2 B1x = *(const float2*)(in2 + 32 + (p / 96u) * 128 + (p % 96u));
    p += 65536u;
    const float2 B1y = *(const float2*)(in2 + 32 + (p / 96u) * 128 + (p % 96u));
    p += 65536u;
    const float2 B1z = *(const float2*)(in2 + 32 + (p / 96u) * 128 + (p % 96u));

    // ---- seg0 / seg1: direct coalesced streaming stores ----
    float2 t2;
    t2.x = K.c000 * A0.x * B0.x;
    t2.y = K.c000 * A0.y * B0.y;
    __stcs((float2*)(orow + q), t2);
    t2.x = K.c330[0] * A1x.x * B1x.x + K.c330[1] * A1y.x * B1y.x + K.c330[2] * A1z.x * B1z.x;
    t2.y = K.c330[0] * A1x.y * B1x.y + K.c330[1] * A1y.y * B1y.y + K.c330[2] * A1z.y * B1z.y;
    __stcs((float2*)(orow + 2048 + q), t2);

    // ---- seg2: 0e x 1o -> 1o (layout q*3+k) @wb+0 ----
    {
        const float a0 = A0.x, b0 = A0.y;
        float2 s;
        s.x = K.c2[0] * a0 * B1x.x;  s.y = K.c2[1] * a0 * B1y.x;
        *(float2*)(wstage + 6 * lane) = s;
        s.x = K.c2[2] * a0 * B1z.x;  s.y = K.c2[0] * b0 * B1x.y;
        *(float2*)(wstage + 6 * lane + 2) = s;
        s.x = K.c2[1] * b0 * B1y.y;  s.y = K.c2[2] * b0 * B1z.y;
        *(float2*)(wstage + 6 * lane + 4) = s;
    }
    // ---- seg3: 1o x 0e -> 1o @wb+192 ----
    {
        const float b0 = B0.x, c0 = B0.y;
        float2 s;
        s.x = K.c101[0] * A1x.x * b0;  s.y = K.c101[1] * A1y.x * b0;
        *(float2*)(wstage + 192 + 6 * lane) = s;
        s.x = K.c101[2] * A1z.x * b0;  s.y = K.c101[0] * A1x.y * c0;
        *(float2*)(wstage + 192 + 6 * lane + 2) = s;
        s.x = K.c101[1] * A1y.y * c0;  s.y = K.c101[2] * A1z.y * c0;
        *(float2*)(wstage + 192 + 6 * lane + 4) = s;
    }
    // ---- seg4: 1o x 1o -> 1e (Levi-Civita) @wb+384 ----
    {
        float2 s;
        s.x = K.c4[0] * A1y.x * B1z.x + K.c4[1] * A1z.x * B1y.x;
        s.y = K.c4[2] * A1x.x * B1z.x + K.c4[3] * A1z.x * B1x.x;
        *(float2*)(wstage + 384 + 6 * lane) = s;
        s.x = K.c4[4] * A1x.x * B1y.x + K.c4[5] * A1y.x * B1x.x;
        s.y = K.c4[0] * A1y.y * B1z.y + K.c4[1] * A1z.y * B1y.y;
        *(float2*)(wstage + 384 + 6 * lane + 2) = s;
        s.x = K.c4[2] * A1x.y * B1z.y + K.c4[3] * A1z.y * B1x.y;
        s.y = K.c4[4] * A1x.y * B1y.y + K.c4[5] * A1y.y * B1x.y;
        *(float2*)(wstage + 384 + 6 * lane + 4) = s;
    }
    // ---- seg5: 1o x 1o -> 2e (layout q*5+k) @wb+576 ----
    {
        float2 s;
        s.x = K.c5[0] * A1x.x * B1z.x + K.c5[1]  * A1z.x * B1x.x;
        s.y = K.c5[2] * A1x.x * B1y.x + K.c5[3]  * A1y.x * B1x.x;
        *(float2*)(wstage + 576 + 10 * lane) = s;
        s.x = K.c5[4] * A1x.x * B1x.x + K.c5[5]  * A1y.x * B1y.x + K.c5[6] * A1z.x * B1z.x;
        s.y = K.c5[7] * A1y.x * B1z.x + K.c5[8]  * A1z.x * B1y.x;
        *(float2*)(wstage + 576 + 10 * lane + 2) = s;
        s.x = K.c5[9] * A1x.x * B1x.x + K.c5[10] * A1z.x * B1z.x;
        s.y = K.c5[0] * A1x.y * B1z.y + K.c5[1]  * A1z.y * B1x.y;
        *(float2*)(wstage + 576 + 10 * lane + 4) = s;
        s.x = K.c5[2] * A1x.y * B1y.y + K.c5[3]  * A1y.y * B1x.y;
        s.y = K.c5[4] * A1x.y * B1x.y + K.c5[5]  * A1y.y * B1y.y + K.c5[6] * A1z.y * B1z.y;
        *(float2*)(wstage + 576 + 10 * lane + 6) = s;
        s.x = K.c5[7] * A1y.y * B1z.y + K.c5[8]  * A1z.y * B1y.y;
        s.y = K.c5[9] * A1x.y * B1x.y + K.c5[10] * A1z.y * B1z.y;
        *(float2*)(wstage + 576 + 10 * lane + 8) = s;
    }

    __syncwarp();   // warp-local: staging visible to flush within this warp

    // ---- flush: warp's own 224 float4 = exactly 7 per lane, coalesced ----
    const float4* const wstage4 = reinterpret_cast<const float4*>(wstage);
    #pragma unroll
    for (int it = 0; it < 7; ++it) {
        const int t = it * 32 + lane;      // 0..223 within warp region
        const float4 val = wstage4[t];
        int addr;
        if (t < 48)       addr = 4096  + qw * 3 + 4 * t;
        else if (t < 96)  addr = 10240 + qw * 3 + 4 * (t - 48);
        else if (t < 144) addr = 16384 + qw * 3 + 4 * (t - 96);
        else              addr = 22528 + qw * 5 + 4 * (t - 144);
        __stcs(reinterpret_cast<float4*>(orow + addr), val);
    }
}

// ---------------------------------------------------------------------------
extern "C" void kernel_launch(void* const* d_in, const int* in_sizes, int n_in,
                              void* d_out, int out_size)
{
    (void)n_in; (void)out_size;
    Consts K = build_consts();                  // pure host math, deterministic
    const float* in1 = (const float*)d_in[0];   // (2048, 256) fp32
    const float* in2 = (const float*)d_in[1];   // (2048, 128) fp32
    float* out = (float*)d_out;                 // (2048, 32768) fp32
    const int rows = in_sizes[0] / 256;         // 2048 output rows == (u,v) pairs
    ftp_kernel<<<rows * 4, 256>>>(in1, in2, out, K);
}

// round 16
// speedup vs baseline: 1.0031x; 1.0008x over previous
#include <cuda_runtime.h>
#include <cmath>
#include <complex>
#include <vector>
#include <algorithm>
#include <cstdint>

// ---------------------------------------------------------------------------
// Host-side exact e3nn real-basis Wigner 3j (mirrors reference_code line by line)
// ---------------------------------------------------------------------------
namespace cgh {
typedef std::complex<double> cd;

static double fct(int n) { double r = 1.0; for (int i = 2; i <= n; ++i) r *= (double)i; return r; }

static double su2_cg_coeff(int j1, int m1, int j2, int m2, int j3, int m3) {
    if (m3 != m1 + m2) return 0.0;
    int vmin = std::max(std::max(-j1 + j2 + m3, -j1 + m1), 0);
    int vmax = std::min(std::min(j2 + j3 + m1, j3 - j1 + j2), j3 + m3);
    double C = std::sqrt((2.0 * j3 + 1.0) * fct(j3 + j1 - j2) * fct(j3 - j1 + j2) * fct(j1 + j2 - j3)
                         * fct(j3 + m3) * fct(j3 - m3)
                         / (fct(j1 + j2 + j3 + 1) * fct(j1 - m1) * fct(j1 + m1) * fct(j2 - m2) * fct(j2 + m2)));
    double S = 0.0;
    for (int v = vmin; v <= vmax; ++v) {
        double sgn = ((v + j2 + m2) & 1) ? -1.0 : 1.0;
        S += sgn * fct(j2 + j3 + m1 - v) * fct(j1 - m1 + v)
             / (fct(v) * fct(j3 - j1 + j2 - v) * fct(j3 + m3 - v) * fct(v + j1 - j2 - m3));
    }
    return C * S;
}

static void su2_cg(int j1, int j2, int j3, double* mat) {
    int d1 = 2 * j1 + 1, d2 = 2 * j2 + 1, d3 = 2 * j3 + 1;
    for (int i = 0; i < d1 * d2 * d3; ++i) mat[i] = 0.0;
    if (std::abs(j1 - j2) <= j3 && j3 <= j1 + j2) {
        for (int m1 = -j1; m1 <= j1; ++m1)
            for (int m2 = -j2; m2 <= j2; ++m2)
                if (std::abs(m1 + m2) <= j3)
                    mat[((j1 + m1) * d2 + (j2 + m2)) * d3 + (j3 + m1 + m2)] =
                        su2_cg_coeff(j1, m1, j2, m2, j3, m1 + m2);
    }
    double s = 1.0 / std::sqrt(2.0 * j3 + 1.0);
    for (int i = 0; i < d1 * d2 * d3; ++i) mat[i] *= s;
}

static void basis_r2c(int l, cd* q) {
    int d = 2 * l + 1;
    for (int i = 0; i < d * d; ++i) q[i] = cd(0, 0);
    const double inv = 1.0 / std::sqrt(2.0);
    for (int m = -l; m < 0; ++m) {
        q[(l + m) * d + (l - m)] = cd(inv, 0);
        q[(l + m) * d + (l + m)] = cd(0, -inv);
    }
    q[l * d + l] = cd(1, 0);
    for (int m = 1; m <= l; ++m) {
        double sgn = (m & 1) ? -1.0 : 1.0;
        q[(l + m) * d + (l + m)] = cd(sgn * inv, 0);
        q[(l + m) * d + (l - m)] = cd(0, sgn * inv);
    }
    cd ph(1, 0), mi(0, -1);
    for (int t = 0; t < l; ++t) ph *= mi;
    for (int i = 0; i < d * d; ++i) q[i] *= ph;
}

static void wigner3j(int l1, int l2, int l3, double* out) {
    int d1 = 2 * l1 + 1, d2 = 2 * l2 + 1, d3 = 2 * l3 + 1;
    std::vector<cd> Q1(d1 * d1), Q2(d2 * d2), Q3(d3 * d3);
    basis_r2c(l1, Q1.data()); basis_r2c(l2, Q2.data()); basis_r2c(l3, Q3.data());
    std::vector<double> C(d1 * d2 * d3);
    su2_cg(l1, l2, l3, C.data());
    double nrm = 0.0;
    for (int j = 0; j < d1; ++j)
        for (int ll = 0; ll < d2; ++ll)
            for (int m = 0; m < d3; ++m) {
                cd s(0, 0);
                for (int i = 0; i < d1; ++i)
                    for (int k = 0; k < d2; ++k)
                        for (int n = 0; n < d3; ++n)
                            s += Q1[i * d1 + j] * Q2[k * d2 + ll] * std::conj(Q3[n * d3 + m])
                                 * C[(i * d2 + k) * d3 + n];
                out[(j * d2 + ll) * d3 + m] = s.real();
                nrm += s.real() * s.real();
            }
    nrm = std::sqrt(nrm);
    for (int i = 0; i < d1 * d2 * d3; ++i) out[i] /= nrm;
}
} // namespace cgh

// ---------------------------------------------------------------------------
struct Consts {
    float c000;
    float c2[3];      // 0e x 1o -> 1o : diag
    float c101[3];    // 1o x 0e -> 1o : diag
    float c330[3];    // 1o x 1o -> 0e : diag
    float c4[6];      // 1o x 1o -> 1e
    float c5[11];     // 1o x 1o -> 2e
};

static Consts build_consts() {
    Consts K;
    const double s3 = std::sqrt(3.0), s5 = std::sqrt(5.0);
    double w000[1];  cgh::wigner3j(0, 0, 0, w000);
    K.c000 = (float)(w000[0]);
    double w011[9];  cgh::wigner3j(0, 1, 1, w011);
    for (int k = 0; k < 3; ++k) K.c2[k] = (float)(w011[k * 3 + k] * s3);
    double w101[9];  cgh::wigner3j(1, 0, 1, w101);
    for (int k = 0; k < 3; ++k) K.c101[k] = (float)(w101[k * 3 + k] * s3);
    double w110[9];  cgh::wigner3j(1, 1, 0, w110);
    for (int i = 0; i < 3; ++i) K.c330[i] = (float)(w110[i * 3 + i]);
    double w111[27]; cgh::wigner3j(1, 1, 1, w111);
    K.c4[0] = (float)(w111[(1 * 3 + 2) * 3 + 0] * s3);
    K.c4[1] = (float)(w111[(2 * 3 + 1) * 3 + 0] * s3);
    K.c4[2] = (float)(w111[(0 * 3 + 2) * 3 + 1] * s3);
    K.c4[3] = (float)(w111[(2 * 3 + 0) * 3 + 1] * s3);
    K.c4[4] = (float)(w111[(0 * 3 + 1) * 3 + 2] * s3);
    K.c4[5] = (float)(w111[(1 * 3 + 0) * 3 + 2] * s3);
    double w112[45]; cgh::wigner3j(1, 1, 2, w112);
    K.c5[0]  = (float)(w112[(0 * 3 + 2) * 5 + 0] * s5);
    K.c5[1]  = (float)(w112[(2 * 3 + 0) * 5 + 0] * s5);
    K.c5[2]  = (float)(w112[(0 * 3 + 1) * 5 + 1] * s5);
    K.c5[3]  = (float)(w112[(1 * 3 + 0) * 5 + 1] * s5);
    K.c5[4]  = (float)(w112[(0 * 3 + 0) * 5 + 2] * s5);
    K.c5[5]  = (float)(w112[(1 * 3 + 1) * 5 + 2] * s5);
    K.c5[6]  = (float)(w112[(2 * 3 + 2) * 5 + 2] * s5);
    K.c5[7]  = (float)(w112[(1 * 3 + 2) * 5 + 3] * s5);
    K.c5[8]  = (float)(w112[(2 * 3 + 1) * 5 + 3] * s5);
    K.c5[9]  = (float)(w112[(0 * 3 + 0) * 5 + 4] * s5);
    K.c5[10] = (float)(w112[(2 * 3 + 2) * 5 + 4] * s5);
    return K;
}

// ---------------------------------------------------------------------------
// FINAL converged kernel (v11). Session result: 45.6 -> 41.0 us, ~81% of HBM
// write spec; five independent design families confirm the DRAM/L2 wall.
// Run-to-run band of this exact configuration: 41.02-41.12 us over 4 runs.
//
// Design facts established this session:
//  - 2 q/thread @ 32 regs is the sweet spot (4 q/thread spills -> 2x slower).
//  - Warp-local smem staging + __syncwarp beats block barriers.
//  - Fire-and-forget __stcs beats TMA bulk stores in steady-state replay
//    (TMA wins single-launch ncu but pays a CTA drain tail every replay).
//  - Occupancy >= ~74% is sufficient; beyond that, timing is flat.
//  - Compiler magic-multiply division beats hand strength-reduction here.
//
// Warp w handles q in [q0 + 64w, q0 + 64w + 64); lane l handles q = base+2l.
// Warp region (float offsets from wb = 896*w):
//   seg2 @wb+0, seg3 @wb+192, seg4 @wb+384 (192 each), seg5 @wb+576 (320).
// Output row segment bases: 0, 2048, 4096, 10240, 16384, 22528.
//
// Gather maps (flat slice pos p -> row-major array index), q even:
//   a0 : u*8192 + (q>>6)*256 + (q&63)
//   a1i: p=(i*64+u)*2048+q ; 64 + (p/192)*256 + p%192
//   b0 : v*8192 + (q>>5)*128 + (q&31)
//   b1i: p=(i*32+v)*2048+q ; 32 + (p/96)*128  + p%96
// ---------------------------------------------------------------------------
__global__ __launch_bounds__(256, 8)
void ftp_kernel(const float* __restrict__ in1, const float* __restrict__ in2,
                float* __restrict__ out, Consts K)
{
    __shared__ __align__(16) float stage[7168];
    const int tid  = threadIdx.x;
    const int lane = tid & 31;
    const int w    = tid >> 5;
    const int bid  = blockIdx.x;
    const int row  = bid >> 2;            // 4 tiles of 512q per row
    const int u = row >> 5;
    const int v = row & 31;
    const int q0 = (bid & 3) << 9;        // tile start in q
    const int qw = q0 + (w << 6);         // warp's 64-q slice start
    const int q  = qw + 2 * lane;         // this thread's (even) q
    float* __restrict__ orow = out + (size_t)row * 32768;
    float* const wstage = stage + w * 896;

    // ---- gathers (all L2/L1-resident, contiguous float2) ----
    const float2 A0 = *(const float2*)(in1 + (u * 8192 + ((q >> 6) << 8) + (q & 63)));
    unsigned p = (unsigned)(u * 2048 + q);
    const float2 A1x = *(const float2*)(in1 + 64 + (p / 192u) * 256 + (p % 192u));
    p += 131072u;
    const float2 A1y = *(const float2*)(in1 + 64 + (p / 192u) * 256 + (p % 192u));
    p += 131072u;
    const float2 A1z = *(const float2*)(in1 + 64 + (p / 192u) * 256 + (p % 192u));
    const float2 B0 = *(const float2*)(in2 + (v * 8192 + ((q >> 5) << 7) + (q & 31)));
    p = (unsigned)(v * 2048 + q);
    const float2 B1x = *(const float2*)(in2 + 32 + (p / 96u) * 128 + (p % 96u));
    p += 65536u;
    const float2 B1y = *(const float2*)(in2 + 32 + (p / 96u) * 128 + (p % 96u));
    p += 65536u;
    const float2 B1z = *(const float2*)(in2 + 32 + (p / 96u) * 128 + (p % 96u));

    // ---- seg0 / seg1: direct coalesced streaming stores ----
    float2 t2;
    t2.x = K.c000 * A0.x * B0.x;
    t2.y = K.c000 * A0.y * B0.y;
    __stcs((float2*)(orow + q), t2);
    t2.x = K.c330[0] * A1x.x * B1x.x + K.c330[1] * A1y.x * B1y.x + K.c330[2] * A1z.x * B1z.x;
    t2.y = K.c330[0] * A1x.y * B1x.y + K.c330[1] * A1y.y * B1y.y + K.c330[2] * A1z.y * B1z.y;
    __stcs((float2*)(orow + 2048 + q), t2);

    // ---- seg2: 0e x 1o -> 1o (layout q*3+k) @wb+0 ----
    {
        const float a0 = A0.x, b0 = A0.y;
        float2 s;
        s.x = K.c2[0] * a0 * B1x.x;  s.y = K.c2[1] * a0 * B1y.x;
        *(float2*)(wstage + 6 * lane) = s;
        s.x = K.c2[2] * a0 * B1z.x;  s.y = K.c2[0] * b0 * B1x.y;
        *(float2*)(wstage + 6 * lane + 2) = s;
        s.x = K.c2[1] * b0 * B1y.y;  s.y = K.c2[2] * b0 * B1z.y;
        *(float2*)(wstage + 6 * lane + 4) = s;
    }
    // ---- seg3: 1o x 0e -> 1o @wb+192 ----
    {
        const float b0 = B0.x, c0 = B0.y;
        float2 s;
        s.x = K.c101[0] * A1x.x * b0;  s.y = K.c101[1] * A1y.x * b0;
        *(float2*)(wstage + 192 + 6 * lane) = s;
        s.x = K.c101[2] * A1z.x * b0;  s.y = K.c101[0] * A1x.y * c0;
        *(float2*)(wstage + 192 + 6 * lane + 2) = s;
        s.x = K.c101[1] * A1y.y * c0;  s.y = K.c101[2] * A1z.y * c0;
        *(float2*)(wstage + 192 + 6 * lane + 4) = s;
    }
    // ---- seg4: 1o x 1o -> 1e (Levi-Civita) @wb+384 ----
    {
        float2 s;
        s.x = K.c4[0] * A1y.x * B1z.x + K.c4[1] * A1z.x * B1y.x;
        s.y = K.c4[2] * A1x.x * B1z.x + K.c4[3] * A1z.x * B1x.x;
        *(float2*)(wstage + 384 + 6 * lane) = s;
        s.x = K.c4[4] * A1x.x * B1y.x + K.c4[5] * A1y.x * B1x.x;
        s.y = K.c4[0] * A1y.y * B1z.y + K.c4[1] * A1z.y * B1y.y;
        *(float2*)(wstage + 384 + 6 * lane + 2) = s;
        s.x = K.c4[2] * A1x.y * B1z.y + K.c4[3] * A1z.y * B1x.y;
        s.y = K.c4[4] * A1x.y * B1y.y + K.c4[5] * A1y.y * B1x.y;
        *(float2*)(wstage + 384 + 6 * lane + 4) = s;
    }
    // ---- seg5: 1o x 1o -> 2e (layout q*5+k) @wb+576 ----
    {
        float2 s;
        s.x = K.c5[0] * A1x.x * B1z.x + K.c5[1]  * A1z.x * B1x.x;
        s.y = K.c5[2] * A1x.x * B1y.x + K.c5[3]  * A1y.x * B1x.x;
        *(float2*)(wstage + 576 + 10 * lane) = s;
        s.x = K.c5[4] * A1x.x * B1x.x + K.c5[5]  * A1y.x * B1y.x + K.c5[6] * A1z.x * B1z.x;
        s.y = K.c5[7] * A1y.x * B1z.x + K.c5[8]  * A1z.x * B1y.x;
        *(float2*)(wstage + 576 + 10 * lane + 2) = s;
        s.x = K.c5[9] * A1x.x * B1x.x + K.c5[10] * A1z.x * B1z.x;
        s.y = K.c5[0] * A1x.y * B1z.y + K.c5[1]  * A1z.y * B1x.y;
        *(float2*)(wstage + 576 + 10 * lane + 4) = s;
        s.x = K.c5[2] * A1x.y * B1y.y + K.c5[3]  * A1y.y * B1x.y;
        s.y = K.c5[4] * A1x.y * B1x.y + K.c5[5]  * A1y.y * B1y.y + K.c5[6] * A1z.y * B1z.y;
        *(float2*)(wstage + 576 + 10 * lane + 6) = s;
        s.x = K.c5[7] * A1y.y * B1z.y + K.c5[8]  * A1z.y * B1y.y;
        s.y = K.c5[9] * A1x.y * B1x.y + K.c5[10] * A1z.y * B1z.y;
        *(float2*)(wstage + 576 + 10 * lane + 8) = s;
    }

    __syncwarp();   // warp-local: staging visible to flush within this warp

    // ---- flush: warp's own 224 float4 = exactly 7 per lane, coalesced ----
    const float4* const wstage4 = reinterpret_cast<const float4*>(wstage);
    #pragma unroll
    for (int it = 0; it < 7; ++it) {
        const int t = it * 32 + lane;      // 0..223 within warp region
        const float4 val = wstage4[t];
        int addr;
        if (t < 48)       addr = 4096  + qw * 3 + 4 * t;
        else if (t < 96)  addr = 10240 + qw * 3 + 4 * (t - 48);
        else if (t < 144) addr = 16384 + qw * 3 + 4 * (t - 96);
        else              addr = 22528 + qw * 5 + 4 * (t - 144);
        __stcs(reinterpret_cast<float4*>(orow + addr), val);
    }
}

// ---------------------------------------------------------------------------
extern "C" void kernel_launch(void* const* d_in, const int* in_sizes, int n_in,
                              void* d_out, int out_size)
{
    (void)n_in; (void)out_size;
    Consts K = build_consts();                  // pure host math, deterministic
    const float* in1 = (const float*)d_in[0];   // (2048, 256) fp32
    const float* in2 = (const float*)d_in[1];   // (2048, 128) fp32
    float* out = (float*)d_out;                 // (2048, 32768) fp32
    const int rows = in_sizes[0] / 256;         // 2048 output rows == (u,v) pairs
    ftp_kernel<<<rows * 4, 256>>>(in1, in2, out, K);
}